// round 2
// baseline (speedup 1.0000x reference)
#include <cuda_runtime.h>
#include <cuda_bf16.h>
#include <cstdint>

// ============================================================================
// simpleRQA: out[n] = any_m( cos_sim(Ex[n], Ey[m]) > 0.9 )
// Ex, Ey: [8192, 1024] fp32.  out: [8192] fp32 (0.0 / 1.0)
//
// K1: normalize rows (fp32 norm, clamp 1e-8) -> bf16 scratch; zero out[].
// K2: bf16 mma.sync GEMM (CTA tile 128x128, BK=64, 3-stage cp.async) fused
//     with threshold (>0.9) + any-over-N reduce.  (tcgen05 is rejected by the
//     harness's compute_100 PTX target, so we use the portable HMMA path.)
// ============================================================================

#define NROWS   8192
#define DIMS    1024
#define BM_     128
#define BN_     128
#define BK_     64                  // bf16 per K chunk (128 bytes/row)
#define NCHUNK  (DIMS / BK_)        // 16
#define STAGES  3
#define GT_     256                 // threads per GEMM CTA (8 warps: 4M x 2N)

#define STAGE_BYTES   (BM_ * 128 + BN_ * 128)   // 32 KB (A 16K + B 16K)
#define SMEM_DYN      (STAGES * STAGE_BYTES + 1024)

// Normalized bf16 operands (static device scratch; 16 MB each), 16B-aligned.
static __device__ uint4 g_Xb4[(size_t)NROWS * DIMS / 8];
static __device__ uint4 g_Yb4[(size_t)NROWS * DIMS / 8];

// ---------------------------------------------------------------------------
// helpers
// ---------------------------------------------------------------------------
static __device__ __forceinline__ uint32_t smem_u32(const void* p) {
    uint32_t a;
    asm("{ .reg .u64 t; cvta.to.shared.u64 t, %1; cvt.u32.u64 %0, t; }"
        : "=r"(a) : "l"(p));
    return a;
}

static __device__ __forceinline__ void cp_async16(uint32_t dst, const void* src) {
    asm volatile("cp.async.cg.shared.global [%0], [%1], 16;"
                 :: "r"(dst), "l"(src) : "memory");
}
#define CP_COMMIT() asm volatile("cp.async.commit_group;" ::: "memory")
#define CP_WAIT(n)  asm volatile("cp.async.wait_group %0;" :: "n"(n) : "memory")

static __device__ __forceinline__ void ldmatrix_x4(
    uint32_t& r0, uint32_t& r1, uint32_t& r2, uint32_t& r3, uint32_t addr) {
    asm volatile("ldmatrix.sync.aligned.m8n8.x4.shared.b16 {%0,%1,%2,%3}, [%4];"
                 : "=r"(r0), "=r"(r1), "=r"(r2), "=r"(r3) : "r"(addr));
}

static __device__ __forceinline__ void mma_bf16(
    float* c, uint32_t a0, uint32_t a1, uint32_t a2, uint32_t a3,
    uint32_t b0, uint32_t b1) {
    asm volatile(
        "mma.sync.aligned.m16n8k16.row.col.f32.bf16.bf16.f32 "
        "{%0,%1,%2,%3}, {%4,%5,%6,%7}, {%8,%9}, {%0,%1,%2,%3};"
        : "+f"(c[0]), "+f"(c[1]), "+f"(c[2]), "+f"(c[3])
        : "r"(a0), "r"(a1), "r"(a2), "r"(a3), "r"(b0), "r"(b1));
}

static __device__ __forceinline__ uint32_t swz(uint32_t off) {
    return off ^ ((off >> 3) & 0x70);   // SW128: conflict-free 128B rows
}

// ---------------------------------------------------------------------------
// K1: per-row normalize fp32 -> bf16, and zero the output flags.
// ---------------------------------------------------------------------------
__global__ void __launch_bounds__(256) rqa_normalize(
    const float* __restrict__ Ex, const float* __restrict__ Ey,
    float* __restrict__ out)
{
    __shared__ float ws[8];
    const int row = blockIdx.x;
    const int tid = threadIdx.x;

    if (tid == 0) out[row] = 0.0f;

    // ---- X row ----
    {
        const float4* px = reinterpret_cast<const float4*>(Ex) + (size_t)row * 256;
        float4 v = px[tid];
        float ss = v.x * v.x + v.y * v.y + v.z * v.z + v.w * v.w;
        #pragma unroll
        for (int o = 16; o > 0; o >>= 1) ss += __shfl_xor_sync(0xFFFFFFFFu, ss, o);
        if ((tid & 31) == 0) ws[tid >> 5] = ss;
        __syncthreads();
        float tot = ws[0] + ws[1] + ws[2] + ws[3] + ws[4] + ws[5] + ws[6] + ws[7];
        float scale = 1.0f / fmaxf(sqrtf(tot), 1e-8f);
        __nv_bfloat162 h0, h1;
        h0.x = __float2bfloat16(v.x * scale); h0.y = __float2bfloat16(v.y * scale);
        h1.x = __float2bfloat16(v.z * scale); h1.y = __float2bfloat16(v.w * scale);
        uint2 u;
        u.x = *reinterpret_cast<uint32_t*>(&h0);
        u.y = *reinterpret_cast<uint32_t*>(&h1);
        reinterpret_cast<uint2*>(g_Xb4)[(size_t)row * 256 + tid] = u;
        __syncthreads();
    }
    // ---- Y row ----
    {
        const float4* py = reinterpret_cast<const float4*>(Ey) + (size_t)row * 256;
        float4 v = py[tid];
        float ss = v.x * v.x + v.y * v.y + v.z * v.z + v.w * v.w;
        #pragma unroll
        for (int o = 16; o > 0; o >>= 1) ss += __shfl_xor_sync(0xFFFFFFFFu, ss, o);
        if ((tid & 31) == 0) ws[tid >> 5] = ss;
        __syncthreads();
        float tot = ws[0] + ws[1] + ws[2] + ws[3] + ws[4] + ws[5] + ws[6] + ws[7];
        float scale = 1.0f / fmaxf(sqrtf(tot), 1e-8f);
        __nv_bfloat162 h0, h1;
        h0.x = __float2bfloat16(v.x * scale); h0.y = __float2bfloat16(v.y * scale);
        h1.x = __float2bfloat16(v.z * scale); h1.y = __float2bfloat16(v.w * scale);
        uint2 u;
        u.x = *reinterpret_cast<uint32_t*>(&h0);
        u.y = *reinterpret_cast<uint32_t*>(&h1);
        reinterpret_cast<uint2*>(g_Yb4)[(size_t)row * 256 + tid] = u;
    }
}

// ---------------------------------------------------------------------------
// K2: bf16 mma.sync GEMM + threshold + any-reduce.
// ---------------------------------------------------------------------------
__global__ void __launch_bounds__(GT_, 2) rqa_gemm(float* __restrict__ out)
{
    extern __shared__ char smem_raw[];
    const uint32_t sb = (smem_u32(smem_raw) + 1023u) & ~1023u;

    const int tid = threadIdx.x;
    const int wid = tid >> 5;
    const int lid = tid & 31;
    const int warp_m = wid & 3;       // 4 M-groups of 32 rows
    const int warp_n = wid >> 2;      // 2 N-groups of 64 cols
    const int tm = blockIdx.x;        // 64 M tiles
    const int tn = blockIdx.y;        // 64 N tiles

    const uint4* Ag = g_Xb4 + (size_t)tm * BM_ * (DIMS / 8);
    const uint4* Bg = g_Yb4 + (size_t)tn * BN_ * (DIMS / 8);

    // per-stage copy: A (128 rows x 8 uint4) then B (128 rows x 8 uint4)
    const int cp_row = tid >> 3;      // 0..31 base row, stepped by 32
    const int cp_v   = tid & 7;       // uint4 index within 128B row

    auto issue_stage = [&](int c, int s) {
        const uint32_t a_base = sb + s * STAGE_BYTES;
        const uint32_t b_base = a_base + BM_ * 128;
        #pragma unroll
        for (int i = 0; i < 4; i++) {
            const int row = cp_row + i * 32;
            const uint32_t off = swz((uint32_t)(row * 128 + cp_v * 16));
            cp_async16(a_base + off, Ag + (size_t)row * (DIMS / 8) + c * 8 + cp_v);
        }
        #pragma unroll
        for (int i = 0; i < 4; i++) {
            const int row = cp_row + i * 32;
            const uint32_t off = swz((uint32_t)(row * 128 + cp_v * 16));
            cp_async16(b_base + off, Bg + (size_t)row * (DIMS / 8) + c * 8 + cp_v);
        }
        CP_COMMIT();
    };

    float acc[2][8][4];
    #pragma unroll
    for (int i = 0; i < 2; i++)
        #pragma unroll
        for (int j = 0; j < 8; j++)
            #pragma unroll
            for (int k = 0; k < 4; k++) acc[i][j][k] = 0.0f;

    // prologue: prefetch 2 chunks
    issue_stage(0, 0);
    issue_stage(1, 1);

    // precomputed ldmatrix lane addressing
    // A (x4): row = warp_m*32 + i*16 + (lid&15); kb = ks*32 + (lid>>4)*16
    const int a_row_l = warp_m * 32 + (lid & 15);
    const int a_kb_l  = (lid >> 4) * 16;
    // B (x4): mat = lid>>3, lrow = lid&7
    //   n = warp_n*64 + j2*16 + ((mat>>1)&1)*8 + lrow ; kb = ks*32 + (mat&1)*16
    const int b_mat  = lid >> 3;
    const int b_n_l  = warp_n * 64 + ((b_mat >> 1) & 1) * 8 + (lid & 7);
    const int b_kb_l = (b_mat & 1) * 16;

    #pragma unroll 1
    for (int c = 0; c < NCHUNK; c++) {
        CP_WAIT(1);
        __syncthreads();

        if (c + 2 < NCHUNK) issue_stage(c + 2, (c + 2) % STAGES);

        const int s = c % STAGES;
        const uint32_t a_base = sb + s * STAGE_BYTES;
        const uint32_t b_base = a_base + BM_ * 128;

        #pragma unroll
        for (int ks = 0; ks < 4; ks++) {
            uint32_t a[2][4];
            #pragma unroll
            for (int i = 0; i < 2; i++) {
                const uint32_t off =
                    swz((uint32_t)((a_row_l + i * 16) * 128 + ks * 32 + a_kb_l));
                ldmatrix_x4(a[i][0], a[i][1], a[i][2], a[i][3], a_base + off);
            }
            uint32_t b[4][4];
            #pragma unroll
            for (int j2 = 0; j2 < 4; j2++) {
                const uint32_t off =
                    swz((uint32_t)((b_n_l + j2 * 16) * 128 + ks * 32 + b_kb_l));
                ldmatrix_x4(b[j2][0], b[j2][1], b[j2][2], b[j2][3], b_base + off);
            }
            #pragma unroll
            for (int i = 0; i < 2; i++)
                #pragma unroll
                for (int j = 0; j < 8; j++) {
                    const int j2 = j >> 1, h = j & 1;
                    mma_bf16(acc[i][j], a[i][0], a[i][1], a[i][2], a[i][3],
                             b[j2][2 * h], b[j2][2 * h + 1]);
                }
        }
    }

    // Epilogue: threshold + OR over this CTA's 128 N columns, then merge the
    // 4-lane quad (tig) so lane tig==0 holds the row verdict.
    #pragma unroll
    for (int i = 0; i < 2; i++) {
        #pragma unroll
        for (int h = 0; h < 2; h++) {
            int f = 0;
            #pragma unroll
            for (int j = 0; j < 8; j++)
                f |= (acc[i][j][2 * h] > 0.9f) | (acc[i][j][2 * h + 1] > 0.9f);
            f |= __shfl_xor_sync(0xFFFFFFFFu, f, 1);
            f |= __shfl_xor_sync(0xFFFFFFFFu, f, 2);
            if ((lid & 3) == 0 && f) {
                const int row = tm * BM_ + warp_m * 32 + i * 16 + h * 8 + (lid >> 2);
                out[row] = 1.0f;   // benign same-value race across tn tiles
            }
        }
    }
}

// ---------------------------------------------------------------------------
// Launch
// ---------------------------------------------------------------------------
extern "C" void kernel_launch(void* const* d_in, const int* in_sizes, int n_in,
                              void* d_out, int out_size)
{
    const float* Ex = (const float*)d_in[0];
    const float* Ey = (const float*)d_in[1];
    float* out = (float*)d_out;

    cudaFuncSetAttribute(rqa_gemm, cudaFuncAttributeMaxDynamicSharedMemorySize, SMEM_DYN);

    rqa_normalize<<<NROWS, 256>>>(Ex, Ey, out);

    dim3 grid(NROWS / BM_, NROWS / BN_);
    rqa_gemm<<<grid, GT_, SMEM_DYN>>>(out);
}